// round 7
// baseline (speedup 1.0000x reference)
#include <cuda_runtime.h>

// PreampGainLayer: DK-method preamp, FFT-domain circular filtering.
// Inputs (metadata order): x[B*2048], cond[B], state[B*4096],
//   alpha_rg[1], alpha_r1[1], alpha_c1[1], alpha_c2[1], cond_w[1], cond_b[1]
// Output: float[B*2048]

#define MM 2048
#define PI_D 3.14159265358979323846

// twiddle table: {sin(pi*k/2048), 1 - cos(pi*k/2048)}
__device__ float2 g_tw[2049];

// bank swizzle: bijective on low 4 bits per 16-aligned block; uses v bits 4..6
__device__ __forceinline__ int SW(int v) {
    return v ^ ((v >> 4) & 7) ^ ((v >> 3) & 8);
}

// ---------------------------------------------------------------------------
// init kernel: twiddle table only (fp32)
// ---------------------------------------------------------------------------
__global__ void init_tw_kernel() {
    int k = blockIdx.x * blockDim.x + threadIdx.x;
    if (k <= 2048) {
        float th = (float)k * (float)(PI_D / 2048.0);
        float s  = sinf(th);
        float hs = sinf(0.5f * th);
        g_tw[k] = make_float2(s, 2.0f * hs * hs);
    }
}

// ---------------------------------------------------------------------------
// per-batch DK params (fp64 chain, cancellation-safe); called by one thread
// ---------------------------------------------------------------------------
__device__ void compute_params(float condv, float argf, float arr1, float arc1,
                               float arc2, float cwv, float cbv,
                               float* __restrict__ sP) {
    auto sigf = [](float v) { return 1.0f / (1.0f + expf(-v)); };

    const double T = 1.0 / 44100.0;
    double RG = (0.9 + (double)sigf(argf) * 0.2) * 1.0e6;
    double R1 = (0.99 + (double)sigf(arr1) * 0.02) * 4.7e5;
    double C1 = (0.9 + (double)sigf(arc1) * 0.2) * 3.3e-9;
    double C2 = (0.9 + (double)sigf(arc2) * 0.2) * 1.0e-9;

    double g = 1.0 / R1;
    double a = 2.0 * C1 / T;
    double h = 2.0 * C2 / T;

    // analytic inverse of S = [[a,-a,0,1],[-a,a+g,0,0],[0,0,h,0],[1,0,0,0]]
    double iag = 1.0 / (a + g);
    double ih  = 1.0 / h;
    double Si[4][4] = {
        {0.0, 0.0,     0.0, 1.0},
        {0.0, iag,     0.0, a * iag},
        {0.0, 0.0,     ih,  0.0},
        {1.0, a * iag, 0.0, -a * g * iag}};

    double PV[4][2], PX[4][2], PU[4];
#pragma unroll
    for (int i = 0; i < 4; i++) {
        PV[i][0] = Si[i][1] - Si[i][2];
        PV[i][1] = Si[i][2];
        PX[i][0] = Si[i][0] - Si[i][1];
        PX[i][1] = Si[i][2];
        PU[i]    = Si[i][3];
    }
    double Q[2][2], Ux[2][2];
#pragma unroll
    for (int c = 0; c < 2; c++) {
        Q[0][c]  = PV[1][c] - PV[2][c];
        Q[1][c]  = PV[2][c];
        Ux[0][c] = PV[0][c] - PV[1][c];
        Ux[1][c] = PV[2][c];
    }
    double UoV[2] = {PV[2][0], PV[2][1]};
    double Uu[2]  = {PV[3][0], PV[3][1]};
    double NXX[2][2];
#pragma unroll
    for (int c = 0; c < 2; c++) { NXX[0][c] = PX[0][c] - PX[1][c]; NXX[1][c] = PX[2][c]; }
    double zg1 = 2.0 * a, zg2 = 2.0 * h;
    double Ao[2][2] = {{zg1 * NXX[0][0] - 1.0, zg1 * NXX[0][1]},
                       {zg2 * NXX[1][0], zg2 * NXX[1][1] - 1.0}};
    double Bo[2] = {zg1 * (PU[0] - PU[1]), zg2 * PU[2]};
    double Do[2] = {PX[2][0], PX[2][1]};
    double Eo = PU[2];

    float potf = sigf(condv * cwv + cbv);
    float pf = (exp10f(potf) - 1.0f) * (1.0f / 9.0f);
    pf = fminf(fmaxf(pf, 1e-4f), 1.0f - 1e-4f);
    double p = (double)pf;
    double d0 = (1.0 - p) * RG, d1 = p * RG;

    double M00 = d0 + Q[0][0], M01 = Q[0][1], M10 = Q[1][0], M11 = d1 + Q[1][1];
    double idet = 1.0 / (M00 * M11 - M01 * M10);
    double K[2][2] = {{M11 * idet, -M01 * idet}, {-M10 * idet, M00 * idet}};

    double ZU[2][2] = {{zg1 * Ux[0][0], zg1 * Ux[0][1]},
                       {zg2 * Ux[1][0], zg2 * Ux[1][1]}};
    double t1[2][2];
#pragma unroll
    for (int r = 0; r < 2; r++)
#pragma unroll
        for (int c = 0; c < 2; c++)
            t1[r][c] = ZU[r][0] * K[0][c] + ZU[r][1] * K[1][c];

    double A2[2][2], Bm[2], Dm[2];
#pragma unroll
    for (int r = 0; r < 2; r++)
#pragma unroll
        for (int c = 0; c < 2; c++)
            A2[r][c] = Ao[r][c] - (t1[r][0] * Ux[c][0] + t1[r][1] * Ux[c][1]);
#pragma unroll
    for (int r = 0; r < 2; r++)
        Bm[r] = Bo[r] - (t1[r][0] * Uu[0] + t1[r][1] * Uu[1]);
    double UoK[2];
#pragma unroll
    for (int c = 0; c < 2; c++)
        UoK[c] = UoV[0] * K[0][c] + UoV[1] * K[1][c];
#pragma unroll
    for (int c = 0; c < 2; c++)
        Dm[c] = Do[c] - (UoK[0] * Ux[c][0] + UoK[1] * Ux[c][1]);
    double Em = Eo - (UoK[0] * Uu[0] + UoK[1] * Uu[1]);

    double tr  = A2[0][0] + A2[1][1];
    double det = A2[0][0] * A2[1][1] - A2[0][1] * A2[1][0];
    double m2[2][2];
#pragma unroll
    for (int r = 0; r < 2; r++)
#pragma unroll
        for (int c = 0; c < 2; c++)
            m2[r][c] = A2[r][c] - Bm[r] * Dm[c];
    double tr2  = m2[0][0] + m2[1][1];
    double det2 = m2[0][0] * m2[1][1] - m2[0][1] * m2[1][0];

    double n0 = Em;
    double n1 = -tr2 - (Em - 1.0) * tr;
    double n2 = det2 + (Em - 1.0) * det;

    sP[0] = (float)(1.0 - tr + det);   // DC
    sP[1] = (float)(1.0 + det);        // DS
    sP[2] = (float)(det - 1.0);        // DI
    sP[3] = (float)(n0 + n1 + n2);     // NC
    sP[4] = (float)(n0 + n2);          // NS
    sP[5] = (float)(n2 - n0);          // NI
}

// ---------------------------------------------------------------------------
// FFT filter kernel: radix-8 register Stockham, one CTA per batch row
// ---------------------------------------------------------------------------

// radix-4 butterfly, DIF/Stockham: twiddles (c1..c3) applied to OUTPUTS.
__device__ __forceinline__ void bfly4(float2 a0, float2 a1, float2 a2, float2 a3,
                                      float c1, float s1, float c2, float s2,
                                      float c3, float s3, float sgn,
                                      float2& o0, float2& o1, float2& o2, float2& o3) {
    float p02x = a0.x + a2.x, p02y = a0.y + a2.y;
    float m02x = a0.x - a2.x, m02y = a0.y - a2.y;
    float p13x = a1.x + a3.x, p13y = a1.y + a3.y;
    float m13x = a1.x - a3.x, m13y = a1.y - a3.y;

    float b1rx = m02x - sgn * m13y, b1ry = m02y + sgn * m13x;
    float b3rx = m02x + sgn * m13y, b3ry = m02y - sgn * m13x;
    float b2rx = p02x - p13x,       b2ry = p02y - p13y;

    o0 = make_float2(p02x + p13x, p02y + p13y);
    o1 = make_float2(c1 * b1rx - s1 * b1ry, c1 * b1ry + s1 * b1rx);
    o2 = make_float2(c2 * b2rx - s2 * b2ry, c2 * b2ry + s2 * b2rx);
    o3 = make_float2(c3 * b3rx - s3 * b3ry, c3 * b3ry + s3 * b3rx);
}

// radix-8 core: radix-4 at m composed with DIF radix-2 at 4m
// (out_low = A+B, out_high = w2*(A-B)).
__device__ __forceinline__ void radix8_core(const float2 a[8], int q, int pm,
                                            float sgn, float2* __restrict__ nxt,
                                            int m) {
    const float r = 0.70710678118654752f;
    float2 w = g_tw[pm << 1];
    float c1 = 1.0f - w.y, s1 = sgn * w.x;
    float c2 = c1 * c1 - s1 * s1, s2 = 2.0f * c1 * s1;
    float c3 = c1 * c2 - s1 * s2, s3 = s1 * c2 + c1 * s2;
    float c1b = r * (c1 - sgn * s1), s1b = r * (sgn * c1 + s1);
    float c2b = -sgn * s2,           s2b = sgn * c2;
    float c3b = r * (-c3 - sgn * s3), s3b = r * (sgn * c3 - s3);
    float2 w2 = g_tw[pm << 3];
    float c2w = 1.0f - w2.y, s2w = sgn * w2.x;

    float2 A[4], B[4];
    bfly4(a[0], a[2], a[4], a[6], c1, s1, c2, s2, c3, s3, sgn,
          A[0], A[1], A[2], A[3]);
    bfly4(a[1], a[3], a[5], a[7], c1b, s1b, c2b, s2b, c3b, s3b, sgn,
          B[0], B[1], B[2], B[3]);

    int o = (pm << 3) + q;
    if (m == 1) {
        int ob = SW(o);
#pragma unroll
        for (int j = 0; j < 4; j++) {
            float sx = A[j].x + B[j].x, sy = A[j].y + B[j].y;
            float dx = A[j].x - B[j].x, dy = A[j].y - B[j].y;
            nxt[ob ^ j]       = make_float2(sx, sy);
            nxt[ob ^ (j + 4)] = make_float2(c2w * dx - s2w * dy,
                                            c2w * dy + s2w * dx);
        }
    } else {
#pragma unroll
        for (int j = 0; j < 4; j++) {
            float sx = A[j].x + B[j].x, sy = A[j].y + B[j].y;
            float dx = A[j].x - B[j].x, dy = A[j].y - B[j].y;
            nxt[SW(o + j * m)]         = make_float2(sx, sy);
            nxt[SW(o + j * m + 4 * m)] = make_float2(c2w * dx - s2w * dy,
                                                     c2w * dy + s2w * dx);
        }
    }
}

__device__ __forceinline__ void radix8_stage(const float2* __restrict__ cur,
                                             float2* __restrict__ nxt,
                                             int t, int m, float sgn) {
    int q  = t & (m - 1);
    int pm = t - q;
    int swt = SW(t);   // SW(t+256j) = SW(t)+256j
    float2 a[8];
#pragma unroll
    for (int j = 0; j < 8; j++) a[j] = cur[swt + 256 * j];
    radix8_core(a, q, pm, sgn, nxt, m);
}

// untangle+filter for one conjugate pair (single reciprocal for both h's)
__device__ __forceinline__ void untangle_pair(float2 Uk, float2 Um, float sn, float omc,
                                              float DC, float DS, float DI,
                                              float NC, float NS, float NI,
                                              float2& outk, float2& outm) {
    float cs = 1.0f - omc;
    float uer = 0.5f * (Uk.x + Um.x), uei = 0.5f * (Uk.y - Um.y);
    float uor = 0.5f * (Uk.y + Um.y), uoi = -0.5f * (Uk.x - Um.x);
    float xr = uer + cs * uor + sn * uoi;
    float xi = uei + cs * uoi - sn * uor;
    float xmr = uer - (cs * uor + sn * uoi);
    float xmi = -uei - (sn * uor - cs * uoi);

    float omc2 = 2.0f - omc;
    float d1r = DC - DS * omc,  d1i = DI * sn;
    float n1r = NC - NS * omc,  n1i = NI * sn;
    float d2r = DC - DS * omc2, n2r = NC - NS * omc2;
    float q1 = d1r * d1r + d1i * d1i;
    float q2 = d2r * d2r + d1i * d1i;
    float inv = 1.0f / (q1 * q2);
    float i1 = inv * q2, i2 = inv * q1;
    float hkx = (n1r * d1r + n1i * d1i) * i1, hky = (n1i * d1r - n1r * d1i) * i1;
    float hmx = (n2r * d2r + n1i * d1i) * i2, hmy = (n1i * d2r - n2r * d1i) * i2;

    float ykr = hkx * xr - hky * xi, yki = hkx * xi + hky * xr;
    float ymr = hmx * xmr - hmy * xmi, ymi = hmx * xmi + hmy * xmr;
    float yer = 0.5f * (ykr + ymr), yei = 0.5f * (yki - ymi);
    float zr  = 0.5f * (ykr - ymr), zi  = 0.5f * (yki + ymi);
    float yor = cs * zr - sn * zi, yoi = cs * zi + sn * zr;
    outk = make_float2(yer - yoi, yei + yor);
    outm = make_float2(yer + yoi, yor - yei);
}

__global__ __launch_bounds__(256, 4) void preamp_fft_kernel(
    const float* __restrict__ x, const float* __restrict__ state,
    const float* __restrict__ cond,
    const float* __restrict__ a_rg, const float* __restrict__ a_r1,
    const float* __restrict__ a_c1, const float* __restrict__ a_c2,
    const float* __restrict__ cw, const float* __restrict__ cb,
    float* __restrict__ out) {
    __shared__ float2 sA[MM];
    __shared__ float2 sB[MM];
    __shared__ float sP[8];

    const int b = blockIdx.x;
    const int t = threadIdx.x;

    // thread 0 computes per-batch DK params while the CTA runs the forward
    // FFT; ordered by the __syncthreads() preceding the untangle.
    if (t == 0) {
        compute_params(cond[b], a_rg[0], a_r1[0], a_c1[0], a_c2[0],
                       cw[0], cb[0], sP);
    }

    const float2* st2 = (const float2*)(state + (size_t)b * 4096 + 2048);
    const float2* x2  = (const float2*)(x + (size_t)b * 2048);

    // ---- forward radix-8 stage m=1 fused with gmem load ----
    {
        float2 a[8];
#pragma unroll
        for (int j = 0; j < 4; j++) a[j] = st2[t + 256 * j];
#pragma unroll
        for (int j = 0; j < 4; j++) a[4 + j] = x2[t + 256 * j];
        radix8_core(a, 0, t, -1.0f, sA, 1);
    }
    __syncthreads();

    // ---- forward radix-8 stages m=8, m=64 ----
    radix8_stage(sA, sB, t, 8, -1.0f);
    __syncthreads();
    radix8_stage(sB, sA, t, 64, -1.0f);
    __syncthreads();
    // remaining unit-twiddle radix-4 (m=512) fused into untangle below.

    const float DC = sP[0], DS = sP[1], DI = sP[2],
                NC = sP[3], NS = sP[4], NI = sP[5];

    // ---- untangle -> rfft bins, * h, repack -> V (into sB) ----
#pragma unroll
    for (int it = 0; it < 2; it++) {
        int q = t + it * 256;
        if (q == 0) {
            float2 g0 = sA[SW(0)], g1 = sA[SW(512)], g2 = sA[SW(1024)], g3 = sA[SW(1536)];
            float p02x = g0.x + g2.x, p02y = g0.y + g2.y;
            float m02x = g0.x - g2.x, m02y = g0.y - g2.y;
            float p13x = g1.x + g3.x, p13y = g1.y + g3.y;
            float m13x = g1.x - g3.x, m13y = g1.y - g3.y;
            float2 U0    = make_float2(p02x + p13x, p02y + p13y);
            float2 U512  = make_float2(m02x + m13y, m02y - m13x);
            float2 U1024 = make_float2(p02x - p13x, p02y - p13y);
            float2 U1536 = make_float2(m02x - m13y, m02y + m13x);
            float X0 = U0.x + U0.y;
            float XM = U0.x - U0.y;
            float h0 = NC / DC;
            float hM = (NC - 2.0f * NS) / (DC - 2.0f * DS);
            float Y0 = h0 * X0, YM = hM * XM;
            sB[SW(0)] = make_float2(0.5f * (Y0 + YM), 0.5f * (Y0 - YM));
            {
                float dr = DC - DS, di = DI;
                float nr = NC - NS, ni = NI;
                float inv = 1.0f / (dr * dr + di * di);
                float hx = (nr * dr + ni * di) * inv;
                float hy = (ni * dr - nr * di) * inv;
                float yr = hx * U1024.x + hy * U1024.y;
                float yi = hy * U1024.x - hx * U1024.y;
                sB[SW(1024)] = make_float2(yr, -yi);
            }
            float2 tw = g_tw[512];
            float2 ok, om;
            untangle_pair(U512, U1536, tw.x, tw.y, DC, DS, DI, NC, NS, NI, ok, om);
            sB[SW(512)]  = ok;
            sB[SW(1536)] = om;
        } else {
            float2 g0 = sA[SW(q)], g1 = sA[SW(q + 512)],
                   g2 = sA[SW(q + 1024)], g3 = sA[SW(q + 1536)];
            float p02x = g0.x + g2.x, p02y = g0.y + g2.y;
            float m02x = g0.x - g2.x, m02y = g0.y - g2.y;
            float p13x = g1.x + g3.x, p13y = g1.y + g3.y;
            float m13x = g1.x - g3.x, m13y = g1.y - g3.y;
            float2 Uq0 = make_float2(p02x + p13x, p02y + p13y);      // U[q]
            float2 Uq1 = make_float2(m02x + m13y, m02y - m13x);      // U[q+512]
            int q2 = 512 - q;
            float2 h0 = sA[SW(q2)], h1 = sA[SW(q2 + 512)],
                   h2 = sA[SW(q2 + 1024)], h3 = sA[SW(q2 + 1536)];
            float P02x = h0.x + h2.x, P02y = h0.y + h2.y;
            float M02x = h0.x - h2.x, M02y = h0.y - h2.y;
            float P13x = h1.x + h3.x, P13y = h1.y + h3.y;
            float M13x = h1.x - h3.x, M13y = h1.y - h3.y;
            float2 Ur2 = make_float2(P02x - P13x, P02y - P13y);      // U[1536-q]
            float2 Ur3 = make_float2(M02x - M13y, M02y + M13x);      // U[2048-q]

            float2 tw1 = g_tw[q];
            float2 ok, om;
            untangle_pair(Uq0, Ur3, tw1.x, tw1.y, DC, DS, DI, NC, NS, NI, ok, om);
            sB[SW(q)]        = ok;
            sB[SW(2048 - q)] = om;

            float2 tw2 = g_tw[512 + q];
            untangle_pair(Uq1, Ur2, tw2.x, tw2.y, DC, DS, DI, NC, NS, NI, ok, om);
            sB[SW(512 + q)]  = ok;
            sB[SW(1536 - q)] = om;
        }
    }
    __syncthreads();

    // ---- inverse radix-8 stages m=1, 8, 64 ----
    radix8_stage(sB, sA, t, 1, 1.0f);
    __syncthreads();
    radix8_stage(sA, sB, t, 8, 1.0f);
    __syncthreads();
    radix8_stage(sB, sA, t, 64, 1.0f);
    __syncthreads();
    // final unit-twiddle radix-4 (m=512) fused into store: outputs j=2,3

    const float scale = 1.0f / 2048.0f;
    float4* o4 = (float4*)(out + (size_t)b * 2048);
    {
        float2 r2[2], r3[2];
#pragma unroll
        for (int u = 0; u < 2; u++) {
            int q = 2 * t + u;
            float2 g0 = sA[SW(q)], g1 = sA[SW(q + 512)],
                   g2 = sA[SW(q + 1024)], g3 = sA[SW(q + 1536)];
            float p02x = g0.x + g2.x, p02y = g0.y + g2.y;
            float m02x = g0.x - g2.x, m02y = g0.y - g2.y;
            float p13x = g1.x + g3.x, p13y = g1.y + g3.y;
            float m13x = g1.x - g3.x, m13y = g1.y - g3.y;
            r2[u] = make_float2((p02x - p13x) * scale, (p02y - p13y) * scale);
            r3[u] = make_float2((m02x + m13y) * scale, (m02y - m13x) * scale);
        }
        o4[t]       = make_float4(r2[0].x, r2[0].y, r2[1].x, r2[1].y);
        o4[256 + t] = make_float4(r3[0].x, r3[0].y, r3[1].x, r3[1].y);
    }
}

// ---------------------------------------------------------------------------
extern "C" void kernel_launch(void* const* d_in, const int* in_sizes, int n_in,
                              void* d_out, int out_size) {
    const float* x     = (const float*)d_in[0];
    const float* cond  = (const float*)d_in[1];
    const float* state = (const float*)d_in[2];
    const float* a_rg  = (const float*)d_in[3];
    const float* a_r1  = (const float*)d_in[4];
    const float* a_c1  = (const float*)d_in[5];
    const float* a_c2  = (const float*)d_in[6];
    const float* cw    = (const float*)d_in[7];
    const float* cb    = (const float*)d_in[8];
    float* out = (float*)d_out;

    int B = in_sizes[1];  // cond has B elements

    init_tw_kernel<<<9, 256>>>();
    preamp_fft_kernel<<<B, 256>>>(x, state, cond, a_rg, a_r1, a_c1, a_c2,
                                  cw, cb, out);
}

// round 8
// speedup vs baseline: 1.4401x; 1.4401x over previous
#include <cuda_runtime.h>

// PreampGainLayer: DK-method preamp, FFT-domain circular filtering.
// Inputs (metadata order): x[B*2048], cond[B], state[B*4096],
//   alpha_rg[1], alpha_r1[1], alpha_c1[1], alpha_c2[1], cond_w[1], cond_b[1]
// Output: float[B*2048]
//
// Closed-form DK parameters (derived symbolically from the sparse incidence
// matrices; verified NC == 0, NS == 0 exactly):
//   a = 2*C1*SR, h = 2*C2*SR, g = 1/R1, u = 1/(a+g), v = 1/h
//   d0 = (1-p)*RG, d1 = p*RG
//   Delta = d1*(d0+u) + v*(d0+d1+u)
//   Em  = a*u*v*d1/Delta          NI = -2*Em
//   W00 = 2ug + 2au^2(d1+v)/Delta ; W11 = 2v(d0+d1+u)/Delta
//   DC  = 4uv(g(d0+d1+u) + au)/Delta     (sum of positives -> fp32-safe)
//   DS  = 2 - (W00+W11) + DC ; DI = DC - (W00+W11)
// Filter: h(e^{i t}) = i*NI*sin(t) / ((DC - DS*(1-cos t)) + i*DI*sin(t))

#define MM 2048
#define PI_D 3.14159265358979323846

// twiddle table: {sin(pi*k/2048), 1 - cos(pi*k/2048)}
__device__ float2 g_tw[2049];

// bank swizzle: bijective on low 4 bits per 16-aligned block; uses v bits 4..6
__device__ __forceinline__ int SW(int v) {
    return v ^ ((v >> 4) & 7) ^ ((v >> 3) & 8);
}

// ---------------------------------------------------------------------------
// init kernel: twiddle table only (fp32)
// ---------------------------------------------------------------------------
__global__ void init_tw_kernel() {
    int k = blockIdx.x * blockDim.x + threadIdx.x;
    if (k <= 2048) {
        float th = (float)k * (float)(PI_D / 2048.0);
        float s  = sinf(th);
        float hs = sinf(0.5f * th);
        g_tw[k] = make_float2(s, 2.0f * hs * hs);
    }
}

// ---------------------------------------------------------------------------
// FFT filter kernel: radix-8 register Stockham, one CTA per batch row
// ---------------------------------------------------------------------------

// radix-4 butterfly, DIF/Stockham: twiddles (c1..c3) applied to OUTPUTS.
__device__ __forceinline__ void bfly4(float2 a0, float2 a1, float2 a2, float2 a3,
                                      float c1, float s1, float c2, float s2,
                                      float c3, float s3, float sgn,
                                      float2& o0, float2& o1, float2& o2, float2& o3) {
    float p02x = a0.x + a2.x, p02y = a0.y + a2.y;
    float m02x = a0.x - a2.x, m02y = a0.y - a2.y;
    float p13x = a1.x + a3.x, p13y = a1.y + a3.y;
    float m13x = a1.x - a3.x, m13y = a1.y - a3.y;

    float b1rx = m02x - sgn * m13y, b1ry = m02y + sgn * m13x;
    float b3rx = m02x + sgn * m13y, b3ry = m02y - sgn * m13x;
    float b2rx = p02x - p13x,       b2ry = p02y - p13y;

    o0 = make_float2(p02x + p13x, p02y + p13y);
    o1 = make_float2(c1 * b1rx - s1 * b1ry, c1 * b1ry + s1 * b1rx);
    o2 = make_float2(c2 * b2rx - s2 * b2ry, c2 * b2ry + s2 * b2rx);
    o3 = make_float2(c3 * b3rx - s3 * b3ry, c3 * b3ry + s3 * b3rx);
}

// radix-8 core: radix-4 at m composed with DIF radix-2 at 4m
// (out_low = A+B, out_high = w2*(A-B)).
__device__ __forceinline__ void radix8_core(const float2 a[8], int q, int pm,
                                            float sgn, float2* __restrict__ nxt,
                                            int m) {
    const float r = 0.70710678118654752f;
    float2 w = g_tw[pm << 1];
    float c1 = 1.0f - w.y, s1 = sgn * w.x;
    float c2 = c1 * c1 - s1 * s1, s2 = 2.0f * c1 * s1;
    float c3 = c1 * c2 - s1 * s2, s3 = s1 * c2 + c1 * s2;
    float c1b = r * (c1 - sgn * s1), s1b = r * (sgn * c1 + s1);
    float c2b = -sgn * s2,           s2b = sgn * c2;
    float c3b = r * (-c3 - sgn * s3), s3b = r * (sgn * c3 - s3);
    float2 w2 = g_tw[pm << 3];
    float c2w = 1.0f - w2.y, s2w = sgn * w2.x;

    float2 A[4], B[4];
    bfly4(a[0], a[2], a[4], a[6], c1, s1, c2, s2, c3, s3, sgn,
          A[0], A[1], A[2], A[3]);
    bfly4(a[1], a[3], a[5], a[7], c1b, s1b, c2b, s2b, c3b, s3b, sgn,
          B[0], B[1], B[2], B[3]);

    int o = (pm << 3) + q;
    if (m == 1) {
        int ob = SW(o);
#pragma unroll
        for (int j = 0; j < 4; j++) {
            float sx = A[j].x + B[j].x, sy = A[j].y + B[j].y;
            float dx = A[j].x - B[j].x, dy = A[j].y - B[j].y;
            nxt[ob ^ j]       = make_float2(sx, sy);
            nxt[ob ^ (j + 4)] = make_float2(c2w * dx - s2w * dy,
                                            c2w * dy + s2w * dx);
        }
    } else {
#pragma unroll
        for (int j = 0; j < 4; j++) {
            float sx = A[j].x + B[j].x, sy = A[j].y + B[j].y;
            float dx = A[j].x - B[j].x, dy = A[j].y - B[j].y;
            nxt[SW(o + j * m)]         = make_float2(sx, sy);
            nxt[SW(o + j * m + 4 * m)] = make_float2(c2w * dx - s2w * dy,
                                                     c2w * dy + s2w * dx);
        }
    }
}

__device__ __forceinline__ void radix8_stage(const float2* __restrict__ cur,
                                             float2* __restrict__ nxt,
                                             int t, int m, float sgn) {
    int q  = t & (m - 1);
    int pm = t - q;
    int swt = SW(t);   // SW(t+256j) = SW(t)+256j
    float2 a[8];
#pragma unroll
    for (int j = 0; j < 8; j++) a[j] = cur[swt + 256 * j];
    radix8_core(a, q, pm, sgn, nxt, m);
}

// untangle+filter for one conjugate pair (numerator is pure i*NI*sin).
__device__ __forceinline__ void untangle_pair(float2 Uk, float2 Um, float sn, float omc,
                                              float DC, float DS, float DI, float NI,
                                              float2& outk, float2& outm) {
    float cs = 1.0f - omc;
    float uer = 0.5f * (Uk.x + Um.x), uei = 0.5f * (Uk.y - Um.y);
    float uor = 0.5f * (Uk.y + Um.y), uoi = -0.5f * (Uk.x - Um.x);
    float xr = uer + cs * uor + sn * uoi;
    float xi = uei + cs * uoi - sn * uor;
    float xmr = uer - (cs * uor + sn * uoi);
    float xmi = -uei - (sn * uor - cs * uoi);

    float ni  = NI * sn;
    float di  = DI * sn;
    float d1r = DC - DS * omc;
    float d2r = DC - DS * (2.0f - omc);
    float q1 = d1r * d1r + di * di;
    float q2 = d2r * d2r + di * di;
    float inv = 1.0f / (q1 * q2);
    float i1 = inv * q2, i2 = inv * q1;
    // h = i*ni / (dr + i*di) = (ni*di + i*ni*dr)/(dr^2+di^2)
    float hkx = ni * di * i1, hky = ni * d1r * i1;
    float hmx = ni * di * i2, hmy = ni * d2r * i2;

    float ykr = hkx * xr - hky * xi, yki = hkx * xi + hky * xr;
    float ymr = hmx * xmr - hmy * xmi, ymi = hmx * xmi + hmy * xmr;
    float yer = 0.5f * (ykr + ymr), yei = 0.5f * (yki - ymi);
    float zr  = 0.5f * (ykr - ymr), zi  = 0.5f * (yki + ymi);
    float yor = cs * zr - sn * zi, yoi = cs * zi + sn * zr;
    outk = make_float2(yer - yoi, yei + yor);
    outm = make_float2(yer + yoi, yor - yei);
}

__global__ __launch_bounds__(256, 4) void preamp_fft_kernel(
    const float* __restrict__ x, const float* __restrict__ state,
    const float* __restrict__ cond,
    const float* __restrict__ a_rg, const float* __restrict__ a_r1,
    const float* __restrict__ a_c1, const float* __restrict__ a_c2,
    const float* __restrict__ cw, const float* __restrict__ cb,
    float* __restrict__ out) {
    __shared__ float2 sA[MM];
    __shared__ float2 sB[MM];

    const int b = blockIdx.x;
    const int t = threadIdx.x;

    // ---- closed-form DK params, fp32, computed by every thread ----
    float DC, DS, DI, NI;
    {
        auto sigf = [](float v) { return 1.0f / (1.0f + expf(-v)); };
        float RG = (0.9f + sigf(a_rg[0]) * 0.2f) * 1.0e6f;
        float R1 = (0.99f + sigf(a_r1[0]) * 0.02f) * 4.7e5f;
        float C1 = (0.9f + sigf(a_c1[0]) * 0.2f) * 3.3e-9f;
        float C2 = (0.9f + sigf(a_c2[0]) * 0.2f) * 1.0e-9f;
        float g = 1.0f / R1;
        float a = 2.0f * C1 * 44100.0f;
        float hh = 2.0f * C2 * 44100.0f;
        float u = 1.0f / (a + g);
        float v = 1.0f / hh;
        float potf = sigf(cond[b] * cw[0] + cb[0]);
        float p = (exp10f(potf) - 1.0f) * (1.0f / 9.0f);
        p = fminf(fmaxf(p, 1e-4f), 1.0f - 1e-4f);
        float d0 = (1.0f - p) * RG, d1 = p * RG;
        float s01u = d0 + d1 + u;
        float Dl = d1 * (d0 + u) + v * s01u;
        float iD = 1.0f / Dl;
        float Em = a * u * v * d1 * iD;
        float W00 = 2.0f * u * g + 2.0f * a * u * u * (d1 + v) * iD;
        float W11 = 2.0f * v * s01u * iD;
        float trW = W00 + W11;
        DC = 4.0f * u * v * (g * s01u + a * u) * iD;
        DS = 2.0f - trW + DC;
        DI = DC - trW;
        NI = -2.0f * Em;
    }

    const float2* st2 = (const float2*)(state + (size_t)b * 4096 + 2048);
    const float2* x2  = (const float2*)(x + (size_t)b * 2048);

    // ---- forward radix-8 stage m=1 fused with gmem load ----
    {
        float2 a[8];
#pragma unroll
        for (int j = 0; j < 4; j++) a[j] = st2[t + 256 * j];
#pragma unroll
        for (int j = 0; j < 4; j++) a[4 + j] = x2[t + 256 * j];
        radix8_core(a, 0, t, -1.0f, sA, 1);
    }
    __syncthreads();

    // ---- forward radix-8 stages m=8, m=64 ----
    radix8_stage(sA, sB, t, 8, -1.0f);
    __syncthreads();
    radix8_stage(sB, sA, t, 64, -1.0f);
    __syncthreads();
    // remaining unit-twiddle radix-4 (m=512) fused into untangle below.

    // ---- untangle -> rfft bins, * h, repack -> V (into sB) ----
#pragma unroll
    for (int it = 0; it < 2; it++) {
        int q = t + it * 256;
        if (q == 0) {
            float2 g0 = sA[SW(0)], g1 = sA[SW(512)], g2 = sA[SW(1024)], g3 = sA[SW(1536)];
            float p02x = g0.x + g2.x, p02y = g0.y + g2.y;
            float m02x = g0.x - g2.x, m02y = g0.y - g2.y;
            float p13x = g1.x + g3.x, p13y = g1.y + g3.y;
            float m13x = g1.x - g3.x, m13y = g1.y - g3.y;
            float2 U512  = make_float2(m02x + m13y, m02y - m13x);
            float2 U1024 = make_float2(p02x - p13x, p02y - p13y);
            float2 U1536 = make_float2(m02x - m13y, m02y + m13x);
            // bins 0 / 2048: numerator is zero at theta = 0 and pi
            sB[SW(0)] = make_float2(0.0f, 0.0f);
            // bin 1024: theta = pi/2 -> sn=1, omc=1
            {
                float dr = DC - DS, di = DI;
                float inv = 1.0f / (dr * dr + di * di);
                float hx = NI * di * inv;
                float hy = NI * dr * inv;
                float yr = hx * U1024.x + hy * U1024.y;
                float yi = hy * U1024.x - hx * U1024.y;
                sB[SW(1024)] = make_float2(yr, -yi);
            }
            float2 tw = g_tw[512];
            float2 ok, om;
            untangle_pair(U512, U1536, tw.x, tw.y, DC, DS, DI, NI, ok, om);
            sB[SW(512)]  = ok;
            sB[SW(1536)] = om;
        } else {
            float2 g0 = sA[SW(q)], g1 = sA[SW(q + 512)],
                   g2 = sA[SW(q + 1024)], g3 = sA[SW(q + 1536)];
            float p02x = g0.x + g2.x, p02y = g0.y + g2.y;
            float m02x = g0.x - g2.x, m02y = g0.y - g2.y;
            float p13x = g1.x + g3.x, p13y = g1.y + g3.y;
            float m13x = g1.x - g3.x, m13y = g1.y - g3.y;
            float2 Uq0 = make_float2(p02x + p13x, p02y + p13y);      // U[q]
            float2 Uq1 = make_float2(m02x + m13y, m02y - m13x);      // U[q+512]
            int q2 = 512 - q;
            float2 h0 = sA[SW(q2)], h1 = sA[SW(q2 + 512)],
                   h2 = sA[SW(q2 + 1024)], h3 = sA[SW(q2 + 1536)];
            float P02x = h0.x + h2.x, P02y = h0.y + h2.y;
            float M02x = h0.x - h2.x, M02y = h0.y - h2.y;
            float P13x = h1.x + h3.x, P13y = h1.y + h3.y;
            float M13x = h1.x - h3.x, M13y = h1.y - h3.y;
            float2 Ur2 = make_float2(P02x - P13x, P02y - P13y);      // U[1536-q]
            float2 Ur3 = make_float2(M02x - M13y, M02y + M13x);      // U[2048-q]

            float2 tw1 = g_tw[q];
            float2 ok, om;
            untangle_pair(Uq0, Ur3, tw1.x, tw1.y, DC, DS, DI, NI, ok, om);
            sB[SW(q)]        = ok;
            sB[SW(2048 - q)] = om;

            float2 tw2 = g_tw[512 + q];
            untangle_pair(Uq1, Ur2, tw2.x, tw2.y, DC, DS, DI, NI, ok, om);
            sB[SW(512 + q)]  = ok;
            sB[SW(1536 - q)] = om;
        }
    }
    __syncthreads();

    // ---- inverse radix-8 stages m=1, 8, 64 ----
    radix8_stage(sB, sA, t, 1, 1.0f);
    __syncthreads();
    radix8_stage(sA, sB, t, 8, 1.0f);
    __syncthreads();
    radix8_stage(sB, sA, t, 64, 1.0f);
    __syncthreads();
    // final unit-twiddle radix-4 (m=512) fused into store: outputs j=2,3

    const float scale = 1.0f / 2048.0f;
    float4* o4 = (float4*)(out + (size_t)b * 2048);
    {
        float2 r2[2], r3[2];
#pragma unroll
        for (int u = 0; u < 2; u++) {
            int q = 2 * t + u;
            float2 g0 = sA[SW(q)], g1 = sA[SW(q + 512)],
                   g2 = sA[SW(q + 1024)], g3 = sA[SW(q + 1536)];
            float p02x = g0.x + g2.x, p02y = g0.y + g2.y;
            float m02x = g0.x - g2.x, m02y = g0.y - g2.y;
            float p13x = g1.x + g3.x, p13y = g1.y + g3.y;
            float m13x = g1.x - g3.x, m13y = g1.y - g3.y;
            r2[u] = make_float2((p02x - p13x) * scale, (p02y - p13y) * scale);
            r3[u] = make_float2((m02x + m13y) * scale, (m02y - m13x) * scale);
        }
        o4[t]       = make_float4(r2[0].x, r2[0].y, r2[1].x, r2[1].y);
        o4[256 + t] = make_float4(r3[0].x, r3[0].y, r3[1].x, r3[1].y);
    }
}

// ---------------------------------------------------------------------------
extern "C" void kernel_launch(void* const* d_in, const int* in_sizes, int n_in,
                              void* d_out, int out_size) {
    const float* x     = (const float*)d_in[0];
    const float* cond  = (const float*)d_in[1];
    const float* state = (const float*)d_in[2];
    const float* a_rg  = (const float*)d_in[3];
    const float* a_r1  = (const float*)d_in[4];
    const float* a_c1  = (const float*)d_in[5];
    const float* a_c2  = (const float*)d_in[6];
    const float* cw    = (const float*)d_in[7];
    const float* cb    = (const float*)d_in[8];
    float* out = (float*)d_out;

    int B = in_sizes[1];  // cond has B elements

    init_tw_kernel<<<9, 256>>>();
    preamp_fft_kernel<<<B, 256>>>(x, state, cond, a_rg, a_r1, a_c1, a_c2,
                                  cw, cb, out);
}

// round 9
// speedup vs baseline: 1.4425x; 1.0017x over previous
#include <cuda_runtime.h>

// PreampGainLayer: DK-method preamp, FFT-domain circular filtering.
// Inputs (metadata order): x[B*2048], cond[B], state[B*4096],
//   alpha_rg[1], alpha_r1[1], alpha_c1[1], alpha_c2[1], cond_w[1], cond_b[1]
// Output: float[B*2048]
//
// Closed-form DK parameters (symbolic; NC == 0, NS == 0 exactly):
//   a = 2*C1*SR, h = 2*C2*SR, g = 1/R1, u = 1/(a+g), v = 1/h
//   d0 = (1-p)*RG, d1 = p*RG
//   Delta = d1*(d0+u) + v*(d0+d1+u)
//   Em  = a*u*v*d1/Delta ;  NI = -2*Em
//   W00 = 2ug + 2au^2(d1+v)/Delta ; W11 = 2v(d0+d1+u)/Delta
//   DC  = 4uv(g(d0+d1+u) + au)/Delta   (sum of positives -> fp32-safe)
//   DS  = 2 - (W00+W11) + DC ; DI = DC - (W00+W11)
// Filter: h(e^{it}) = i*NI*sin t / ((DC - DS*(1-cos t)) + i*DI*sin t)

#define MM 2048
#define PI_D 3.14159265358979323846

// twiddle table: {sin(pi*k/2048), 1 - cos(pi*k/2048)}
__device__ float2 g_tw[2049];
// batch-invariant constants:
//   [0] = (u, v, RG, g)
//   [1] = (2ug, 2au^2, auv, 4uv)
//   [2] = (au, 2v, cond_w, cond_b)
__device__ float4 g_cvec[3];

// bank swizzle: bijective on low 4 bits per 16-aligned block; uses v bits 4..6
__device__ __forceinline__ int SW(int v) {
    return v ^ ((v >> 4) & 7) ^ ((v >> 3) & 8);
}

// ---------------------------------------------------------------------------
// init kernel: twiddle table + batch-invariant DK constants
// ---------------------------------------------------------------------------
__global__ void init_tw_kernel(const float* __restrict__ a_rg,
                               const float* __restrict__ a_r1,
                               const float* __restrict__ a_c1,
                               const float* __restrict__ a_c2,
                               const float* __restrict__ cw,
                               const float* __restrict__ cb) {
    int k = blockIdx.x * blockDim.x + threadIdx.x;
    if (k <= 2048) {
        float th = (float)k * (float)(PI_D / 2048.0);
        float s  = sinf(th);
        float hs = sinf(0.5f * th);
        g_tw[k] = make_float2(s, 2.0f * hs * hs);
    }
    if (k == 0) {
        auto sigf = [](float v) { return 1.0f / (1.0f + expf(-v)); };
        float RG = (0.9f + sigf(a_rg[0]) * 0.2f) * 1.0e6f;
        float R1 = (0.99f + sigf(a_r1[0]) * 0.02f) * 4.7e5f;
        float C1 = (0.9f + sigf(a_c1[0]) * 0.2f) * 3.3e-9f;
        float C2 = (0.9f + sigf(a_c2[0]) * 0.2f) * 1.0e-9f;
        float g = 1.0f / R1;
        float a = 2.0f * C1 * 44100.0f;
        float hh = 2.0f * C2 * 44100.0f;
        float u = 1.0f / (a + g);
        float v = 1.0f / hh;
        g_cvec[0] = make_float4(u, v, RG, g);
        g_cvec[1] = make_float4(2.0f * u * g, 2.0f * a * u * u,
                                a * u * v, 4.0f * u * v);
        g_cvec[2] = make_float4(a * u, 2.0f * v, cw[0], cb[0]);
    }
}

// ---------------------------------------------------------------------------
// FFT filter kernel: radix-8 register Stockham, one CTA per batch row
// ---------------------------------------------------------------------------

// radix-4 butterfly, DIF/Stockham: twiddles (c1..c3) applied to OUTPUTS.
__device__ __forceinline__ void bfly4(float2 a0, float2 a1, float2 a2, float2 a3,
                                      float c1, float s1, float c2, float s2,
                                      float c3, float s3, float sgn,
                                      float2& o0, float2& o1, float2& o2, float2& o3) {
    float p02x = a0.x + a2.x, p02y = a0.y + a2.y;
    float m02x = a0.x - a2.x, m02y = a0.y - a2.y;
    float p13x = a1.x + a3.x, p13y = a1.y + a3.y;
    float m13x = a1.x - a3.x, m13y = a1.y - a3.y;

    float b1rx = m02x - sgn * m13y, b1ry = m02y + sgn * m13x;
    float b3rx = m02x + sgn * m13y, b3ry = m02y - sgn * m13x;
    float b2rx = p02x - p13x,       b2ry = p02y - p13y;

    o0 = make_float2(p02x + p13x, p02y + p13y);
    o1 = make_float2(c1 * b1rx - s1 * b1ry, c1 * b1ry + s1 * b1rx);
    o2 = make_float2(c2 * b2rx - s2 * b2ry, c2 * b2ry + s2 * b2rx);
    o3 = make_float2(c3 * b3rx - s3 * b3ry, c3 * b3ry + s3 * b3rx);
}

// radix-8 core: radix-4 at m composed with DIF radix-2 at 4m
// (out_low = A+B, out_high = w2*(A-B)).
__device__ __forceinline__ void radix8_core(const float2 a[8], int q, int pm,
                                            float sgn, float2* __restrict__ nxt,
                                            int m) {
    const float r = 0.70710678118654752f;
    float2 w = g_tw[pm << 1];
    float c1 = 1.0f - w.y, s1 = sgn * w.x;
    float c2 = c1 * c1 - s1 * s1, s2 = 2.0f * c1 * s1;
    float c3 = c1 * c2 - s1 * s2, s3 = s1 * c2 + c1 * s2;
    float c1b = r * (c1 - sgn * s1), s1b = r * (sgn * c1 + s1);
    float c2b = -sgn * s2,           s2b = sgn * c2;
    float c3b = r * (-c3 - sgn * s3), s3b = r * (sgn * c3 - s3);
    float2 w2 = g_tw[pm << 3];
    float c2w = 1.0f - w2.y, s2w = sgn * w2.x;

    float2 A[4], B[4];
    bfly4(a[0], a[2], a[4], a[6], c1, s1, c2, s2, c3, s3, sgn,
          A[0], A[1], A[2], A[3]);
    bfly4(a[1], a[3], a[5], a[7], c1b, s1b, c2b, s2b, c3b, s3b, sgn,
          B[0], B[1], B[2], B[3]);

    int o = (pm << 3) + q;
    if (m == 1) {
        int ob = SW(o);
#pragma unroll
        for (int j = 0; j < 4; j++) {
            float sx = A[j].x + B[j].x, sy = A[j].y + B[j].y;
            float dx = A[j].x - B[j].x, dy = A[j].y - B[j].y;
            nxt[ob ^ j]       = make_float2(sx, sy);
            nxt[ob ^ (j + 4)] = make_float2(c2w * dx - s2w * dy,
                                            c2w * dy + s2w * dx);
        }
    } else {
#pragma unroll
        for (int j = 0; j < 4; j++) {
            float sx = A[j].x + B[j].x, sy = A[j].y + B[j].y;
            float dx = A[j].x - B[j].x, dy = A[j].y - B[j].y;
            nxt[SW(o + j * m)]         = make_float2(sx, sy);
            nxt[SW(o + j * m + 4 * m)] = make_float2(c2w * dx - s2w * dy,
                                                     c2w * dy + s2w * dx);
        }
    }
}

__device__ __forceinline__ void radix8_stage(const float2* __restrict__ cur,
                                             float2* __restrict__ nxt,
                                             int t, int m, float sgn) {
    int q  = t & (m - 1);
    int pm = t - q;
    int swt = SW(t);   // SW(t+256j) = SW(t)+256j
    float2 a[8];
#pragma unroll
    for (int j = 0; j < 8; j++) a[j] = cur[swt + 256 * j];
    radix8_core(a, q, pm, sgn, nxt, m);
}

// untangle+filter for one conjugate pair (numerator is pure i*NI*sin).
__device__ __forceinline__ void untangle_pair(float2 Uk, float2 Um, float sn, float omc,
                                              float DC, float DS, float DI, float NI,
                                              float2& outk, float2& outm) {
    float cs = 1.0f - omc;
    float uer = 0.5f * (Uk.x + Um.x), uei = 0.5f * (Uk.y - Um.y);
    float uor = 0.5f * (Uk.y + Um.y), uoi = -0.5f * (Uk.x - Um.x);
    float xr = uer + cs * uor + sn * uoi;
    float xi = uei + cs * uoi - sn * uor;
    float xmr = uer - (cs * uor + sn * uoi);
    float xmi = -uei - (sn * uor - cs * uoi);

    float ni  = NI * sn;
    float di  = DI * sn;
    float d1r = DC - DS * omc;
    float d2r = DC - DS * (2.0f - omc);
    float q1 = d1r * d1r + di * di;
    float q2 = d2r * d2r + di * di;
    float inv = 1.0f / (q1 * q2);
    float i1 = inv * q2, i2 = inv * q1;
    // h = i*ni / (dr + i*di) = (ni*di + i*ni*dr)/(dr^2+di^2)
    float hkx = ni * di * i1, hky = ni * d1r * i1;
    float hmx = ni * di * i2, hmy = ni * d2r * i2;

    float ykr = hkx * xr - hky * xi, yki = hkx * xi + hky * xr;
    float ymr = hmx * xmr - hmy * xmi, ymi = hmx * xmi + hmy * xmr;
    float yer = 0.5f * (ykr + ymr), yei = 0.5f * (yki - ymi);
    float zr  = 0.5f * (ykr - ymr), zi  = 0.5f * (yki + ymi);
    float yor = cs * zr - sn * zi, yoi = cs * zi + sn * zr;
    outk = make_float2(yer - yoi, yei + yor);
    outm = make_float2(yer + yoi, yor - yei);
}

__global__ __launch_bounds__(256, 4) void preamp_fft_kernel(
    const float* __restrict__ x, const float* __restrict__ state,
    const float* __restrict__ cond, float* __restrict__ out) {
    __shared__ float2 sA[MM];
    __shared__ float2 sB[MM];

    const int b = blockIdx.x;
    const int t = threadIdx.x;

    // ---- per-batch DK params: 2 transcendentals + ~15 FMAs ----
    float DC, DS, DI, NI;
    {
        float4 k0 = g_cvec[0], k1 = g_cvec[1], k2 = g_cvec[2];
        float u = k0.x, v = k0.y, RG = k0.z, g = k0.w;
        float potf = 1.0f / (1.0f + expf(-(cond[b] * k2.z + k2.w)));
        float p = (exp10f(potf) - 1.0f) * (1.0f / 9.0f);
        p = fminf(fmaxf(p, 1e-4f), 1.0f - 1e-4f);
        float d0 = (1.0f - p) * RG, d1 = p * RG;
        float s01u = d0 + d1 + u;
        float Dl = d1 * (d0 + u) + v * s01u;
        float iD = 1.0f / Dl;
        float Em  = k1.z * d1 * iD;                    // auv*d1/Dl
        float W00 = k1.x + k1.y * (d1 + v) * iD;       // 2ug + 2au^2(d1+v)/Dl
        float W11 = k2.y * s01u * iD;                  // 2v*s01u/Dl
        float trW = W00 + W11;
        DC = k1.w * (g * s01u + k2.x) * iD;            // 4uv(g*s01u + au)/Dl
        DS = 2.0f - trW + DC;
        DI = DC - trW;
        NI = -2.0f * Em;
    }

    const float2* st2 = (const float2*)(state + (size_t)b * 4096 + 2048);
    const float2* x2  = (const float2*)(x + (size_t)b * 2048);

    // ---- forward radix-8 stage m=1 fused with gmem load ----
    {
        float2 a[8];
#pragma unroll
        for (int j = 0; j < 4; j++) a[j] = st2[t + 256 * j];
#pragma unroll
        for (int j = 0; j < 4; j++) a[4 + j] = x2[t + 256 * j];
        radix8_core(a, 0, t, -1.0f, sA, 1);
    }
    __syncthreads();

    // ---- forward radix-8 stages m=8, m=64 ----
    radix8_stage(sA, sB, t, 8, -1.0f);
    __syncthreads();
    radix8_stage(sB, sA, t, 64, -1.0f);
    __syncthreads();
    // remaining unit-twiddle radix-4 (m=512) fused into untangle below.

    // ---- untangle -> rfft bins, * h, repack -> V (into sB) ----
#pragma unroll
    for (int it = 0; it < 2; it++) {
        int q = t + it * 256;
        if (q == 0) {
            float2 g0 = sA[SW(0)], g1 = sA[SW(512)], g2 = sA[SW(1024)], g3 = sA[SW(1536)];
            float p02x = g0.x + g2.x, p02y = g0.y + g2.y;
            float m02x = g0.x - g2.x, m02y = g0.y - g2.y;
            float p13x = g1.x + g3.x, p13y = g1.y + g3.y;
            float m13x = g1.x - g3.x, m13y = g1.y - g3.y;
            float2 U512  = make_float2(m02x + m13y, m02y - m13x);
            float2 U1024 = make_float2(p02x - p13x, p02y - p13y);
            float2 U1536 = make_float2(m02x - m13y, m02y + m13x);
            // bins 0 / 2048: numerator is zero at theta = 0 and pi
            sB[SW(0)] = make_float2(0.0f, 0.0f);
            // bin 1024: theta = pi/2 -> sn=1, omc=1
            {
                float dr = DC - DS, di = DI;
                float inv = 1.0f / (dr * dr + di * di);
                float hx = NI * di * inv;
                float hy = NI * dr * inv;
                float yr = hx * U1024.x + hy * U1024.y;
                float yi = hy * U1024.x - hx * U1024.y;
                sB[SW(1024)] = make_float2(yr, -yi);
            }
            float2 tw = g_tw[512];
            float2 ok, om;
            untangle_pair(U512, U1536, tw.x, tw.y, DC, DS, DI, NI, ok, om);
            sB[SW(512)]  = ok;
            sB[SW(1536)] = om;
        } else {
            float2 g0 = sA[SW(q)], g1 = sA[SW(q + 512)],
                   g2 = sA[SW(q + 1024)], g3 = sA[SW(q + 1536)];
            float p02x = g0.x + g2.x, p02y = g0.y + g2.y;
            float m02x = g0.x - g2.x, m02y = g0.y - g2.y;
            float p13x = g1.x + g3.x, p13y = g1.y + g3.y;
            float m13x = g1.x - g3.x, m13y = g1.y - g3.y;
            float2 Uq0 = make_float2(p02x + p13x, p02y + p13y);      // U[q]
            float2 Uq1 = make_float2(m02x + m13y, m02y - m13x);      // U[q+512]
            int q2 = 512 - q;
            float2 h0 = sA[SW(q2)], h1 = sA[SW(q2 + 512)],
                   h2 = sA[SW(q2 + 1024)], h3 = sA[SW(q2 + 1536)];
            float P02x = h0.x + h2.x, P02y = h0.y + h2.y;
            float M02x = h0.x - h2.x, M02y = h0.y - h2.y;
            float P13x = h1.x + h3.x, P13y = h1.y + h3.y;
            float M13x = h1.x - h3.x, M13y = h1.y - h3.y;
            float2 Ur2 = make_float2(P02x - P13x, P02y - P13y);      // U[1536-q]
            float2 Ur3 = make_float2(M02x - M13y, M02y + M13x);      // U[2048-q]

            float2 tw1 = g_tw[q];
            float2 ok, om;
            untangle_pair(Uq0, Ur3, tw1.x, tw1.y, DC, DS, DI, NI, ok, om);
            sB[SW(q)]        = ok;
            sB[SW(2048 - q)] = om;

            float2 tw2 = g_tw[512 + q];
            untangle_pair(Uq1, Ur2, tw2.x, tw2.y, DC, DS, DI, NI, ok, om);
            sB[SW(512 + q)]  = ok;
            sB[SW(1536 - q)] = om;
        }
    }
    __syncthreads();

    // ---- inverse radix-8 stages m=1, 8, 64 ----
    radix8_stage(sB, sA, t, 1, 1.0f);
    __syncthreads();
    radix8_stage(sA, sB, t, 8, 1.0f);
    __syncthreads();
    radix8_stage(sB, sA, t, 64, 1.0f);
    __syncthreads();
    // final unit-twiddle radix-4 (m=512) fused into store: outputs j=2,3

    const float scale = 1.0f / 2048.0f;
    float4* o4 = (float4*)(out + (size_t)b * 2048);
    {
        float2 r2[2], r3[2];
#pragma unroll
        for (int u = 0; u < 2; u++) {
            int q = 2 * t + u;
            float2 g0 = sA[SW(q)], g1 = sA[SW(q + 512)],
                   g2 = sA[SW(q + 1024)], g3 = sA[SW(q + 1536)];
            float p02x = g0.x + g2.x, p02y = g0.y + g2.y;
            float m02x = g0.x - g2.x, m02y = g0.y - g2.y;
            float p13x = g1.x + g3.x, p13y = g1.y + g3.y;
            float m13x = g1.x - g3.x, m13y = g1.y - g3.y;
            r2[u] = make_float2((p02x - p13x) * scale, (p02y - p13y) * scale);
            r3[u] = make_float2((m02x + m13y) * scale, (m02y - m13x) * scale);
        }
        o4[t]       = make_float4(r2[0].x, r2[0].y, r2[1].x, r2[1].y);
        o4[256 + t] = make_float4(r3[0].x, r3[0].y, r3[1].x, r3[1].y);
    }
}

// ---------------------------------------------------------------------------
extern "C" void kernel_launch(void* const* d_in, const int* in_sizes, int n_in,
                              void* d_out, int out_size) {
    const float* x     = (const float*)d_in[0];
    const float* cond  = (const float*)d_in[1];
    const float* state = (const float*)d_in[2];
    const float* a_rg  = (const float*)d_in[3];
    const float* a_r1  = (const float*)d_in[4];
    const float* a_c1  = (const float*)d_in[5];
    const float* a_c2  = (const float*)d_in[6];
    const float* cw    = (const float*)d_in[7];
    const float* cb    = (const float*)d_in[8];
    float* out = (float*)d_out;

    int B = in_sizes[1];  // cond has B elements

    init_tw_kernel<<<9, 256>>>(a_rg, a_r1, a_c1, a_c2, cw, cb);
    preamp_fft_kernel<<<B, 256>>>(x, state, cond, out);
}